// round 6
// baseline (speedup 1.0000x reference)
#include <cuda_runtime.h>

#define Bb   1024
#define Nn   512
#define Mm   128
#define CD   1024
#define ODIM 390
#define KSPLIT 8
#define KCH  (CD / KSPLIT)
#define CACHE_ROWS 192          // 3 of every 8 rows cached in smem

// scratch (allowed: __device__ global arrays)
__device__ float g_part[KSPLIT * Bb * ODIM];   // split-K partial sums

__device__ __forceinline__ float sigmoidf_(float x) { return 1.f / (1.f + expf(-x)); }
__device__ __forceinline__ float softplusf_(float x) {
    return fmaxf(x, 0.f) + log1pf(expf(-fabsf(x)));
}

// cached iff (n & 7) < 3 ; compact cache slot
__device__ __forceinline__ int cache_idx(int n) { return (n >> 3) * 3 + (n & 7); }

// ------------------------------------------------------------------
// Kernel 1: split-K GEMM partials. KSPLIT=8 -> 896 CTAs.
// ------------------------------------------------------------------
#define BM 64
#define BN 64
#define BK 16

__global__ __launch_bounds__(256) void fc_gemm(const float* __restrict__ hid,
                                               const float* __restrict__ W) {
    __shared__ float as[BK][BM + 4];
    __shared__ float ws[BK][BN + 4];

    const int b0 = blockIdx.x * BM;
    const int j0 = blockIdx.y * BN;
    const int z  = blockIdx.z;
    const int k0 = z * KCH;
    const int tid = threadIdx.x;
    const int ty = tid >> 4;
    const int tx = tid & 15;
    const int r  = tid >> 2;
    const int q  = (tid & 3) * 4;

    float acc[4][4] = {};

    float4 ha = *(const float4*)&hid[(size_t)(b0 + r) * CD + k0 + q];
    float4 wa = make_float4(0.f, 0.f, 0.f, 0.f);
    if (j0 + r < ODIM)
        wa = *(const float4*)&W[(size_t)(j0 + r) * CD + k0 + q];

    for (int kc = 0; kc < KCH; kc += BK) {
        as[q + 0][r] = ha.x; as[q + 1][r] = ha.y;
        as[q + 2][r] = ha.z; as[q + 3][r] = ha.w;
        ws[q + 0][r] = wa.x; ws[q + 1][r] = wa.y;
        ws[q + 2][r] = wa.z; ws[q + 3][r] = wa.w;
        __syncthreads();

        if (kc + BK < KCH) {
            ha = *(const float4*)&hid[(size_t)(b0 + r) * CD + k0 + kc + BK + q];
            if (j0 + r < ODIM)
                wa = *(const float4*)&W[(size_t)(j0 + r) * CD + k0 + kc + BK + q];
        }

        #pragma unroll
        for (int kk = 0; kk < BK; kk++) {
            float4 av = *(float4*)&as[kk][ty * 4];
            float4 bv = *(float4*)&ws[kk][tx * 4];
            float a[4] = {av.x, av.y, av.z, av.w};
            float b[4] = {bv.x, bv.y, bv.z, bv.w};
            #pragma unroll
            for (int i = 0; i < 4; i++)
                #pragma unroll
                for (int j = 0; j < 4; j++)
                    acc[i][j] += a[i] * b[j];
        }
        __syncthreads();
    }

    float* __restrict__ op = g_part + (size_t)z * Bb * ODIM;
    #pragma unroll
    for (int i = 0; i < 4; i++) {
        int bb = b0 + ty * 4 + i;
        #pragma unroll
        for (int j = 0; j < 4; j++) {
            int jj = j0 + tx * 4 + j;
            if (jj < ODIM)
                op[(size_t)bb * ODIM + jj] = acc[i][j];
        }
    }
}

// ------------------------------------------------------------------
// Kernel 2: fused NTM write head, interleaved smem cache.
// ------------------------------------------------------------------
__device__ __forceinline__ float block_reduce_sum(float v, float* red) {
    int lane = threadIdx.x & 31, wid = threadIdx.x >> 5;
    #pragma unroll
    for (int off = 16; off; off >>= 1) v += __shfl_xor_sync(0xffffffffu, v, off);
    if (lane == 0) red[wid] = v;
    __syncthreads();
    if (wid == 0) {
        float x = (lane < 16) ? red[lane] : 0.f;
        #pragma unroll
        for (int off = 8; off; off >>= 1) x += __shfl_xor_sync(0xffffffffu, x, off);
        if (lane == 0) red[16] = x;
    }
    __syncthreads();
    float r = red[16];
    __syncthreads();
    return r;
}

__device__ __forceinline__ float block_reduce_max(float v, float* red) {
    int lane = threadIdx.x & 31, wid = threadIdx.x >> 5;
    #pragma unroll
    for (int off = 16; off; off >>= 1)
        v = fmaxf(v, __shfl_xor_sync(0xffffffffu, v, off));
    if (lane == 0) red[wid] = v;
    __syncthreads();
    if (wid == 0) {
        float x = (lane < 16) ? red[lane] : -3.4e38f;
        #pragma unroll
        for (int off = 8; off; off >>= 1)
            x = fmaxf(x, __shfl_xor_sync(0xffffffffu, x, off));
        if (lane == 0) red[16] = x;
    }
    __syncthreads();
    float r = red[16];
    __syncthreads();
    return r;
}

__global__ __launch_bounds__(512, 2) void ntm_fused(const float* __restrict__ w_pre,
                                                    const float* __restrict__ memory,
                                                    const float* __restrict__ bias,
                                                    float* __restrict__ out_w,
                                                    float* __restrict__ out_mem) {
    extern __shared__ float smem[];
    float* cache = smem;                           // CACHE_ROWS * 128
    float* Ksm   = smem + CACHE_ROWS * Mm;         // 512 (K, later final w)
    float* wgsm  = Ksm + Nn;                       // 512
    float* k_e   = wgsm + Nn;                      // 128
    float* evec  = k_e + Mm;                       // 128
    float* avec  = evec + Mm;                      // 128
    float* red   = avec + Mm;                      // 32

    __shared__ float s_beta, s_g, s_s0, s_s1, s_s2, s_gamma, s_knorm;
    __shared__ float s_raw[3];

    const int b = blockIdx.x;
    const int tid = threadIdx.x;
    const int lane = tid & 31, wid = tid >> 5;

    // ---- phase 0: reduce split-K partials + activations ----
    if (tid < ODIM) {
        const size_t off = (size_t)b * ODIM + tid;
        float v = bias[tid];
        #pragma unroll
        for (int z = 0; z < KSPLIT; z++)
            v += g_part[(size_t)z * Bb * ODIM + off];
        int j = tid;
        if (j < 128)            k_e[j] = v + 1e-16f;
        else if (j == 128)      s_beta = softplusf_(v);
        else if (j == 129)      s_g    = sigmoidf_(v);
        else if (j <= 132)      s_raw[j - 130] = v;
        else if (j == 133)      s_gamma = 1.f + softplusf_(v);
        else if (j < 262)       evec[j - 134] = sigmoidf_(v);
        else                    avec[j - 262] = v;
    }
    __syncthreads();
    if (tid == 0) {
        float x0 = s_raw[0], x1 = s_raw[1], x2 = s_raw[2];
        float mx = fmaxf(x0, fmaxf(x1, x2));
        float e0 = expf(x0 - mx), e1 = expf(x1 - mx), e2 = expf(x2 - mx);
        float inv = 1.f / (e0 + e1 + e2);
        s_s0 = e0 * inv; s_s1 = e1 * inv; s_s2 = e2 * inv;
    }
    {   // ||k + eps||
        float v = (tid < Mm) ? k_e[tid] * k_e[tid] : 0.f;
        float ss = block_reduce_sum(v, red);
        if (tid == 0) s_knorm = sqrtf(ss);
        __syncthreads();
    }
    const float knorm = s_knorm;
    const float4 kv = *(const float4*)&k_e[lane * 4];
    const float* __restrict__ memb = memory + (size_t)b * Nn * Mm;

    // ---- phase 1: cosine sim, warp per row, 4 rows in flight; cache 3/8 ----
    const int n_base = wid * 32;
    #pragma unroll 1
    for (int i = 0; i < 32; i += 4) {
        const int n = n_base + i;
        float4 m0 = __ldg((const float4*)(memb + (size_t)(n + 0) * Mm) + lane);
        float4 m1 = __ldg((const float4*)(memb + (size_t)(n + 1) * Mm) + lane);
        float4 m2 = __ldg((const float4*)(memb + (size_t)(n + 2) * Mm) + lane);
        float4 m3 = __ldg((const float4*)(memb + (size_t)(n + 3) * Mm) + lane);
        // n_base % 32 == 0 so n&7 == i&7: cached rows are the first 3 of
        // each aligned group of 8 -> only when (i & 7) == 0
        if ((i & 7) == 0) {
            *((float4*)(cache + (size_t)cache_idx(n + 0) * Mm) + lane) = m0;
            *((float4*)(cache + (size_t)cache_idx(n + 1) * Mm) + lane) = m1;
            *((float4*)(cache + (size_t)cache_idx(n + 2) * Mm) + lane) = m2;
        }
        #pragma unroll
        for (int qq = 0; qq < 4; qq++) {
            float4 m4 = (qq == 0) ? m0 : (qq == 1) ? m1 : (qq == 2) ? m2 : m3;
            float x0 = m4.x + 1e-16f, x1 = m4.y + 1e-16f;
            float x2 = m4.z + 1e-16f, x3 = m4.w + 1e-16f;
            float num = x0 * kv.x + x1 * kv.y + x2 * kv.z + x3 * kv.w;
            float ss  = x0 * x0 + x1 * x1 + x2 * x2 + x3 * x3;
            #pragma unroll
            for (int off = 16; off; off >>= 1) {
                num += __shfl_xor_sync(0xffffffffu, num, off);
                ss  += __shfl_xor_sync(0xffffffffu, ss, off);
            }
            if (lane == 0) {
                float denom = sqrtf(ss) * knorm;
                Ksm[n + qq] = num / fmaxf(denom, 1e-8f);
            }
        }
    }
    __syncthreads();

    // ---- phase 2: softmax + interpolate + shift + sharpen + normalize ----
    const int n = tid;
    float bk = s_beta * Ksm[n];
    float mx = block_reduce_max(bk, red);
    float p = expf(bk - mx);
    float psum = block_reduce_sum(p, red);
    float wc = p / psum;
    float g = s_g;
    float wg = g * wc + (1.f - g) * __ldg(&w_pre[(size_t)b * Nn + n]);
    wgsm[n] = wg;
    __syncthreads();
    float wsh = s_s0 * wgsm[(n + Nn - 1) & (Nn - 1)]
              + s_s1 * wg
              + s_s2 * wgsm[(n + 1) & (Nn - 1)];
    float wsp = powf(wsh, s_gamma);
    float wsum = block_reduce_sum(wsp, red);
    float w = wsp / (wsum + 1e-16f);
    out_w[(size_t)b * Nn + n] = w;
    Ksm[n] = w;                 // final w for phase 3
    __syncthreads();

    // ---- phase 3: erase/add. Each warp: 20 global rows + 12 smem rows ----
    const float4 ev = *((const float4*)evec + lane);
    const float4 av = *((const float4*)avec + lane);
    float* __restrict__ omb = out_mem + (size_t)b * Nn * Mm;

    // uncached rows (n&7 in 3..7): 4 groups x 5 rows = 20, pipeline 4 deep
    #pragma unroll 1
    for (int j = 0; j < 20; j += 4) {
        int r0 = n_base + ((j + 0) / 5) * 8 + 3 + ((j + 0) % 5);
        int r1 = n_base + ((j + 1) / 5) * 8 + 3 + ((j + 1) % 5);
        int r2 = n_base + ((j + 2) / 5) * 8 + 3 + ((j + 2) % 5);
        int r3 = n_base + ((j + 3) / 5) * 8 + 3 + ((j + 3) % 5);
        float4 m0 = __ldcs((const float4*)(memb + (size_t)r0 * Mm) + lane);
        float4 m1 = __ldcs((const float4*)(memb + (size_t)r1 * Mm) + lane);
        float4 m2 = __ldcs((const float4*)(memb + (size_t)r2 * Mm) + lane);
        float4 m3 = __ldcs((const float4*)(memb + (size_t)r3 * Mm) + lane);
        #pragma unroll
        for (int qq = 0; qq < 4; qq++) {
            float4 mv = (qq == 0) ? m0 : (qq == 1) ? m1 : (qq == 2) ? m2 : m3;
            int nr = (qq == 0) ? r0 : (qq == 1) ? r1 : (qq == 2) ? r2 : r3;
            float wn = Ksm[nr];
            float4 r;
            r.x = mv.x * (1.f - wn * ev.x) + wn * av.x;
            r.y = mv.y * (1.f - wn * ev.y) + wn * av.y;
            r.z = mv.z * (1.f - wn * ev.z) + wn * av.z;
            r.w = mv.w * (1.f - wn * ev.w) + wn * av.w;
            __stcs((float4*)(omb + (size_t)nr * Mm) + lane, r);
        }
    }
    // cached rows (n&7 in 0..2): 4 groups x 3 rows = 12
    #pragma unroll 1
    for (int gi = 0; gi < 4; gi++) {
        #pragma unroll
        for (int c = 0; c < 3; c++) {
            const int nr = n_base + gi * 8 + c;
            float wn = Ksm[nr];
            float4 mv = *((const float4*)(cache + (size_t)cache_idx(nr) * Mm) + lane);
            float4 r;
            r.x = mv.x * (1.f - wn * ev.x) + wn * av.x;
            r.y = mv.y * (1.f - wn * ev.y) + wn * av.y;
            r.z = mv.z * (1.f - wn * ev.z) + wn * av.z;
            r.w = mv.w * (1.f - wn * ev.w) + wn * av.w;
            __stcs((float4*)(omb + (size_t)nr * Mm) + lane, r);
        }
    }
}

// ------------------------------------------------------------------
extern "C" void kernel_launch(void* const* d_in, const int* in_sizes, int n_in,
                              void* d_out, int out_size) {
    const float* hid    = (const float*)d_in[0];
    const float* w_pre  = (const float*)d_in[1];
    const float* memory = (const float*)d_in[2];
    const float* W_fc   = (const float*)d_in[3];
    const float* b_fc   = (const float*)d_in[4];
    float* out = (float*)d_out;
    float* out_w   = out;
    float* out_mem = out + (size_t)Bb * Nn;

    const int dyn_smem = (CACHE_ROWS * Mm + Nn + Nn + Mm + Mm + Mm + 32) * 4;
    static bool attr_set = false;
    if (!attr_set) {
        cudaFuncSetAttribute(ntm_fused, cudaFuncAttributeMaxDynamicSharedMemorySize,
                             dyn_smem);
        attr_set = true;
    }

    fc_gemm<<<dim3(Bb / BM, (ODIM + BN - 1) / BN, KSPLIT), 256>>>(hid, W_fc);
    ntm_fused<<<Bb, 512, dyn_smem>>>(w_pre, memory, b_fc, out_w, out_mem);
}

// round 7
// speedup vs baseline: 1.0387x; 1.0387x over previous
#include <cuda_runtime.h>

#define Bb   1024
#define Nn   512
#define Mm   128
#define CD   1024
#define ODIM 390
#define KSPLIT 4
#define KCH  (CD / KSPLIT)
#define CACHE_ROWS 128          // 8 rows per warp cached in smem

// scratch (allowed: __device__ global arrays)
__device__ float g_part[KSPLIT * Bb * ODIM];   // split-K partial sums

__device__ __forceinline__ float sigmoidf_(float x) { return 1.f / (1.f + expf(-x)); }
__device__ __forceinline__ float softplusf_(float x) {
    return fmaxf(x, 0.f) + log1pf(expf(-fabsf(x)));
}

// ------------------------------------------------------------------
// Kernel 1: split-K GEMM partials. KSPLIT=4 -> 448 CTAs (one full wave).
// ------------------------------------------------------------------
#define BM 64
#define BN 64
#define BK 16

__global__ __launch_bounds__(256) void fc_gemm(const float* __restrict__ hid,
                                               const float* __restrict__ W) {
    __shared__ float as[BK][BM + 4];
    __shared__ float ws[BK][BN + 4];

    const int b0 = blockIdx.x * BM;
    const int j0 = blockIdx.y * BN;
    const int z  = blockIdx.z;
    const int k0 = z * KCH;
    const int tid = threadIdx.x;
    const int ty = tid >> 4;
    const int tx = tid & 15;
    const int r  = tid >> 2;
    const int q  = (tid & 3) * 4;

    float acc[4][4] = {};

    float4 ha = *(const float4*)&hid[(size_t)(b0 + r) * CD + k0 + q];
    float4 wa = make_float4(0.f, 0.f, 0.f, 0.f);
    if (j0 + r < ODIM)
        wa = *(const float4*)&W[(size_t)(j0 + r) * CD + k0 + q];

    for (int kc = 0; kc < KCH; kc += BK) {
        as[q + 0][r] = ha.x; as[q + 1][r] = ha.y;
        as[q + 2][r] = ha.z; as[q + 3][r] = ha.w;
        ws[q + 0][r] = wa.x; ws[q + 1][r] = wa.y;
        ws[q + 2][r] = wa.z; ws[q + 3][r] = wa.w;
        __syncthreads();

        if (kc + BK < KCH) {
            ha = *(const float4*)&hid[(size_t)(b0 + r) * CD + k0 + kc + BK + q];
            if (j0 + r < ODIM)
                wa = *(const float4*)&W[(size_t)(j0 + r) * CD + k0 + kc + BK + q];
        }

        #pragma unroll
        for (int kk = 0; kk < BK; kk++) {
            float4 av = *(float4*)&as[kk][ty * 4];
            float4 bv = *(float4*)&ws[kk][tx * 4];
            float a[4] = {av.x, av.y, av.z, av.w};
            float b[4] = {bv.x, bv.y, bv.z, bv.w};
            #pragma unroll
            for (int i = 0; i < 4; i++)
                #pragma unroll
                for (int j = 0; j < 4; j++)
                    acc[i][j] += a[i] * b[j];
        }
        __syncthreads();
    }

    float* __restrict__ op = g_part + (size_t)z * Bb * ODIM;
    #pragma unroll
    for (int i = 0; i < 4; i++) {
        int bb = b0 + ty * 4 + i;
        #pragma unroll
        for (int j = 0; j < 4; j++) {
            int jj = j0 + tx * 4 + j;
            if (jj < ODIM)
                op[(size_t)bb * ODIM + jj] = acc[i][j];
        }
    }
}

// ------------------------------------------------------------------
// Kernel 2: fused NTM write head. 3 CTAs/SM, 16-lanes-per-row phase 1.
// ------------------------------------------------------------------
__device__ __forceinline__ float block_reduce_sum(float v, float* red) {
    int lane = threadIdx.x & 31, wid = threadIdx.x >> 5;
    #pragma unroll
    for (int off = 16; off; off >>= 1) v += __shfl_xor_sync(0xffffffffu, v, off);
    if (lane == 0) red[wid] = v;
    __syncthreads();
    if (wid == 0) {
        float x = (lane < 16) ? red[lane] : 0.f;
        #pragma unroll
        for (int off = 8; off; off >>= 1) x += __shfl_xor_sync(0xffffffffu, x, off);
        if (lane == 0) red[16] = x;
    }
    __syncthreads();
    float r = red[16];
    __syncthreads();
    return r;
}

__device__ __forceinline__ float block_reduce_max(float v, float* red) {
    int lane = threadIdx.x & 31, wid = threadIdx.x >> 5;
    #pragma unroll
    for (int off = 16; off; off >>= 1)
        v = fmaxf(v, __shfl_xor_sync(0xffffffffu, v, off));
    if (lane == 0) red[wid] = v;
    __syncthreads();
    if (wid == 0) {
        float x = (lane < 16) ? red[lane] : -3.4e38f;
        #pragma unroll
        for (int off = 8; off; off >>= 1)
            x = fmaxf(x, __shfl_xor_sync(0xffffffffu, x, off));
        if (lane == 0) red[16] = x;
    }
    __syncthreads();
    float r = red[16];
    __syncthreads();
    return r;
}

__global__ __launch_bounds__(512, 3) void ntm_fused(const float* __restrict__ w_pre,
                                                    const float* __restrict__ memory,
                                                    const float* __restrict__ bias,
                                                    float* __restrict__ out_w,
                                                    float* __restrict__ out_mem) {
    extern __shared__ float smem[];
    float* cache = smem;                           // CACHE_ROWS * 128 (64 KB)
    float* Ksm   = smem + CACHE_ROWS * Mm;         // 512 (K, later final w)
    float* wgsm  = Ksm + Nn;                       // 512
    float* k_e   = wgsm + Nn;                      // 128
    float* evec  = k_e + Mm;                       // 128
    float* avec  = evec + Mm;                      // 128
    float* red   = avec + Mm;                      // 32

    __shared__ float s_beta, s_g, s_s0, s_s1, s_s2, s_gamma, s_knorm;
    __shared__ float s_raw[3];

    const int b = blockIdx.x;
    const int tid = threadIdx.x;
    const int lane = tid & 31, wid = tid >> 5;

    // ---- phase 0: reduce split-K partials + activations ----
    if (tid < ODIM) {
        const size_t off = (size_t)b * ODIM + tid;
        float v = bias[tid];
        #pragma unroll
        for (int z = 0; z < KSPLIT; z++)
            v += g_part[(size_t)z * Bb * ODIM + off];
        int j = tid;
        if (j < 128)            k_e[j] = v + 1e-16f;
        else if (j == 128)      s_beta = softplusf_(v);
        else if (j == 129)      s_g    = sigmoidf_(v);
        else if (j <= 132)      s_raw[j - 130] = v;
        else if (j == 133)      s_gamma = 1.f + softplusf_(v);
        else if (j < 262)       evec[j - 134] = sigmoidf_(v);
        else                    avec[j - 262] = v;
    }
    __syncthreads();
    if (tid == 0) {
        float x0 = s_raw[0], x1 = s_raw[1], x2 = s_raw[2];
        float mx = fmaxf(x0, fmaxf(x1, x2));
        float e0 = expf(x0 - mx), e1 = expf(x1 - mx), e2 = expf(x2 - mx);
        float inv = 1.f / (e0 + e1 + e2);
        s_s0 = e0 * inv; s_s1 = e1 * inv; s_s2 = e2 * inv;
    }
    {   // ||k + eps||
        float v = (tid < Mm) ? k_e[tid] * k_e[tid] : 0.f;
        float ss = block_reduce_sum(v, red);
        if (tid == 0) s_knorm = sqrtf(ss);
        __syncthreads();
    }
    const float knorm = s_knorm;
    const float* __restrict__ memb = memory + (size_t)b * Nn * Mm;
    const int n_base = wid * 32;

    // ---- phase 1: cosine sim. 16 lanes per row, 4 rows in flight. ----
    // lane = half*16 + xh; lane covers cols [xh*4, xh*4+4) and [64+xh*4, ...)
    {
        const int xh = lane & 15;
        const int half = lane >> 4;
        const float4 ka = *(const float4*)&k_e[xh * 4];
        const float4 kb = *(const float4*)&k_e[64 + xh * 4];

        #pragma unroll 1
        for (int i = 0; i < 32; i += 4) {
            const int n = n_base + i;
            const float* r0 = memb + (size_t)(n + half) * Mm;
            const float* r1 = memb + (size_t)(n + 2 + half) * Mm;
            float4 a0 = __ldg((const float4*)r0 + xh);
            float4 b0 = __ldg((const float4*)(r0 + 64) + xh);
            float4 a1 = __ldg((const float4*)r1 + xh);
            float4 b1 = __ldg((const float4*)(r1 + 64) + xh);

            if (i < 8) {   // cache this warp's first 8 rows
                float* c0 = cache + (size_t)(wid * 8 + i + half) * Mm;
                float* c1 = cache + (size_t)(wid * 8 + i + 2 + half) * Mm;
                *((float4*)c0 + xh) = a0;
                *((float4*)(c0 + 64) + xh) = b0;
                *((float4*)c1 + xh) = a1;
                *((float4*)(c1 + 64) + xh) = b1;
            }

            #pragma unroll
            for (int p = 0; p < 2; p++) {
                float4 va = p ? a1 : b0, vb;
                // select pair p's data
                float4 A = p ? a1 : a0;
                float4 B = p ? b1 : b0;
                float num = 0.f, ss = 0.f, x;
                x = A.x + 1e-16f; num = fmaf(x, ka.x, num); ss = fmaf(x, x, ss);
                x = A.y + 1e-16f; num = fmaf(x, ka.y, num); ss = fmaf(x, x, ss);
                x = A.z + 1e-16f; num = fmaf(x, ka.z, num); ss = fmaf(x, x, ss);
                x = A.w + 1e-16f; num = fmaf(x, ka.w, num); ss = fmaf(x, x, ss);
                x = B.x + 1e-16f; num = fmaf(x, kb.x, num); ss = fmaf(x, x, ss);
                x = B.y + 1e-16f; num = fmaf(x, kb.y, num); ss = fmaf(x, x, ss);
                x = B.z + 1e-16f; num = fmaf(x, kb.z, num); ss = fmaf(x, x, ss);
                x = B.w + 1e-16f; num = fmaf(x, kb.w, num); ss = fmaf(x, x, ss);
                #pragma unroll
                for (int off = 1; off <= 8; off <<= 1) {
                    num += __shfl_xor_sync(0xffffffffu, num, off);
                    ss  += __shfl_xor_sync(0xffffffffu, ss, off);
                }
                if (xh == 0) {
                    float denom = sqrtf(ss) * knorm;
                    Ksm[n + 2 * p + half] = num / fmaxf(denom, 1e-8f);
                }
                (void)va; (void)vb;
            }
        }
    }
    __syncthreads();

    // ---- phase 2: softmax + interpolate + shift + sharpen + normalize ----
    const int n = tid;
    float bk = s_beta * Ksm[n];
    float mx = block_reduce_max(bk, red);
    float p = expf(bk - mx);
    float psum = block_reduce_sum(p, red);
    float wc = p / psum;
    float g = s_g;
    float wg = g * wc + (1.f - g) * __ldg(&w_pre[(size_t)b * Nn + n]);
    wgsm[n] = wg;
    __syncthreads();
    float wsh = s_s0 * wgsm[(n + Nn - 1) & (Nn - 1)]
              + s_s1 * wg
              + s_s2 * wgsm[(n + 1) & (Nn - 1)];
    float wsp = powf(wsh, s_gamma);
    float wsum = block_reduce_sum(wsp, red);
    float w = wsp / (wsum + 1e-16f);
    out_w[(size_t)b * Nn + n] = w;
    Ksm[n] = w;                 // final w for phase 3
    __syncthreads();

    // ---- phase 3: erase/add. Each warp: 24 global rows + 8 smem rows ----
    const float4 ev = *((const float4*)evec + lane);
    const float4 av = *((const float4*)avec + lane);
    float* __restrict__ omb = out_mem + (size_t)b * Nn * Mm;

    // global rows (offsets 8..31), warp-per-row, 4 deep
    #pragma unroll 1
    for (int j = 8; j < 32; j += 4) {
        const int nr = n_base + j;
        float4 m0 = __ldcs((const float4*)(memb + (size_t)(nr + 0) * Mm) + lane);
        float4 m1 = __ldcs((const float4*)(memb + (size_t)(nr + 1) * Mm) + lane);
        float4 m2 = __ldcs((const float4*)(memb + (size_t)(nr + 2) * Mm) + lane);
        float4 m3 = __ldcs((const float4*)(memb + (size_t)(nr + 3) * Mm) + lane);
        #pragma unroll
        for (int qq = 0; qq < 4; qq++) {
            float4 mv = (qq == 0) ? m0 : (qq == 1) ? m1 : (qq == 2) ? m2 : m3;
            float wn = Ksm[nr + qq];
            float4 r;
            r.x = mv.x * (1.f - wn * ev.x) + wn * av.x;
            r.y = mv.y * (1.f - wn * ev.y) + wn * av.y;
            r.z = mv.z * (1.f - wn * ev.z) + wn * av.z;
            r.w = mv.w * (1.f - wn * ev.w) + wn * av.w;
            __stcs((float4*)(omb + (size_t)(nr + qq) * Mm) + lane, r);
        }
    }
    // cached rows (offsets 0..7) from smem
    #pragma unroll 2
    for (int r8 = 0; r8 < 8; r8++) {
        const int nr = n_base + r8;
        float wn = Ksm[nr];
        float4 mv = *((const float4*)(cache + (size_t)(wid * 8 + r8) * Mm) + lane);
        float4 r;
        r.x = mv.x * (1.f - wn * ev.x) + wn * av.x;
        r.y = mv.y * (1.f - wn * ev.y) + wn * av.y;
        r.z = mv.z * (1.f - wn * ev.z) + wn * av.z;
        r.w = mv.w * (1.f - wn * ev.w) + wn * av.w;
        __stcs((float4*)(omb + (size_t)nr * Mm) + lane, r);
    }
}

// ------------------------------------------------------------------
extern "C" void kernel_launch(void* const* d_in, const int* in_sizes, int n_in,
                              void* d_out, int out_size) {
    const float* hid    = (const float*)d_in[0];
    const float* w_pre  = (const float*)d_in[1];
    const float* memory = (const float*)d_in[2];
    const float* W_fc   = (const float*)d_in[3];
    const float* b_fc   = (const float*)d_in[4];
    float* out = (float*)d_out;
    float* out_w   = out;
    float* out_mem = out + (size_t)Bb * Nn;

    const int dyn_smem = (CACHE_ROWS * Mm + Nn + Nn + Mm + Mm + Mm + 32) * 4;
    static bool attr_set = false;
    if (!attr_set) {
        cudaFuncSetAttribute(ntm_fused, cudaFuncAttributeMaxDynamicSharedMemorySize,
                             dyn_smem);
        attr_set = true;
    }

    fc_gemm<<<dim3(Bb / BM, (ODIM + BN - 1) / BN, KSPLIT), 256>>>(hid, W_fc);
    ntm_fused<<<Bb, 512, dyn_smem>>>(w_pre, memory, b_fc, out_w, out_mem);
}